// round 17
// baseline (speedup 1.0000x reference)
#include <cuda_runtime.h>

#define BATCH 32
#define SEQ   512
#define HID   256
#define TMEL  2000
#define H4    (HID / 4)       // 64 float4 per row
#define CHUNK 16              // input rows per CTA (8 groups x 2 rows)
#define NCHUNK (SEQ / CHUNK)  // 32 CTAs per batch
#define NTHR  512

__global__ __launch_bounds__(NTHR, 4)
void length_regulator_kernel(const float* __restrict__ x,
                             const int* __restrict__ duration,
                             float* __restrict__ out,
                             int out_size) {
    const int b     = blockIdx.y;
    const int chunk = blockIdx.x;        // 0..31
    const int tid   = threadIdx.x;       // 0..511
    const int wid   = tid >> 5;          // 0..15
    const int lane5 = tid & 31;
    const int lane  = tid & 63;          // float4 slot within a row
    const int grp   = tid >> 6;          // 0..7 (row group, 2 rows each)

    __shared__ int csum[SEQ];
    __shared__ int wsum[16];

    // ---- dur load first (heads the dependent scan chain); independent
    //      x-row loads fill its latency shadow. One duration per thread. ----
    const int* durb = duration + b * SEQ;
    int d = durb[tid];

    const float4* __restrict__ xb = (const float4*)x + (b * SEQ) * H4;
    const int r0 = chunk * CHUNK + grp * 2;       // rows r0, r0+1
    float4 v0    = __ldg(&xb[(r0 + 0) * H4 + lane]);
    float4 v1    = __ldg(&xb[(r0 + 1) * H4 + lane]);

    // ---- Inclusive scan of 512 durations: warp scan + 16-warp combine. ----
    int sc = d;
    #pragma unroll
    for (int off = 1; off < 32; off <<= 1) {
        int t = __shfl_up_sync(0xffffffffu, sc, off);
        if (lane5 >= off) sc += t;
    }
    if (lane5 == 31) wsum[wid] = sc;
    __syncthreads();
    int wprefix = 0;
    #pragma unroll
    for (int w = 0; w < 16; w++)
        wprefix += (w < wid) ? wsum[w] : 0;
    csum[tid] = sc + wprefix;            // inclusive cumsum at element tid
    __syncthreads();

    // ---- Input-driven expansion: row i covers output rows
    //      [csum[i-1], csum[i]); dynamic loops (fastest measured form). ----
    float4* __restrict__ ob = (float4*)out + (b * TMEL) * H4;
    {
        int lo0 = (r0 == 0) ? 0 : csum[r0 - 1];
        int hi0 = min(csum[r0], TMEL);
        int hi1 = min(csum[r0 + 1], TMEL);
        for (int t = lo0; t < hi0; t++)
            ob[t * H4 + lane] = v0;
        for (int t = hi0; t < hi1; t++)
            ob[t * H4 + lane] = v1;
    }

    // ---- Tail: positions [total, TMEL) replicate row SEQ-1. Spread across
    //      the 256 (chunk,grp) slots of this batch, stride 256. ----
    int tc = min(csum[SEQ - 1], TMEL);
    int tstart = tc + chunk * 8 + grp;
    if (tstart < TMEL) {
        float4 vlast = __ldg(&xb[(SEQ - 1) * H4 + lane]);
        for (int t = tstart; t < TMEL; t += 8 * NCHUNK)
            ob[t * H4 + lane] = vlast;
    }

    // ---- mel_len appended after main output (if buffer includes it). ----
    if (chunk == 0 && tid == 0) {
        const int main_elems = BATCH * TMEL * HID;
        if (out_size >= main_elems + BATCH)
            out[main_elems + b] = (float)tc;
    }
}

extern "C" void kernel_launch(void* const* d_in, const int* in_sizes, int n_in,
                              void* d_out, int out_size) {
    const float* x        = (const float*)d_in[0];
    const int*   duration = (const int*)d_in[1];
    float*       out      = (float*)d_out;

    dim3 grid(NCHUNK, BATCH);   // (32, 32) = 1024 CTAs x 512 threads
    length_regulator_kernel<<<grid, NTHR>>>(x, duration, out, out_size);
}